// round 14
// baseline (speedup 1.0000x reference)
#include <cuda_runtime.h>
#include <cuda_fp16.h>

// NormalShader fused, R14: main kernel identical to R10/R13 (33.3us). Pack
// split into (a) coalesced vnorm->float4 expand, (b) face pack using 3x
// LDG.128 single-line gathers -> pack wavefront count cut 3x.

#define K_SAMP 8
#define BLK 256
#define PPT 2
#define F_MAX 200000
#define V_MAX 100000

struct __align__(32) PackedFace {
    uint4 a;   // h0..h7 = n0x n0y n0z n1x n1y n1z n2x n2y
    uint4 b;   // b.x low half = n2z; rest pad (never read)
};

__device__ PackedFace g_packed[F_MAX];   // 6.4 MB, L2-resident
__device__ float4     g_vnorm4[V_MAX];   // 1.6 MB, 16B-aligned vertex normals

// Stage A: coalesced reshape vnorm (V,3) -> float4 (V)
__global__ __launch_bounds__(256)
void expand_vnorm_kernel(const float* __restrict__ vnorm, int V)
{
    int v = blockIdx.x * blockDim.x + threadIdx.x;
    if (v >= V) return;
    g_vnorm4[v] = make_float4(vnorm[v * 3 + 0], vnorm[v * 3 + 1],
                              vnorm[v * 3 + 2], 0.0f);
}

// Stage B: per face, 3 single-line LDG.128 gathers -> fp16 packed entry.
__global__ __launch_bounds__(256)
void pack_faces_kernel(const int* __restrict__ faces, int F)
{
    int f = blockIdx.x * blockDim.x + threadIdx.x;
    if (f >= F) return;
    int v0 = faces[f * 3 + 0];
    int v1 = faces[f * 3 + 1];
    int v2 = faces[f * 3 + 2];
    float4 n0 = g_vnorm4[v0];
    float4 n1 = g_vnorm4[v1];
    float4 n2 = g_vnorm4[v2];

    __half2 h01 = __floats2half2_rn(n0.x, n0.y);
    __half2 h23 = __floats2half2_rn(n0.z, n1.x);
    __half2 h45 = __floats2half2_rn(n1.y, n1.z);
    __half2 h67 = __floats2half2_rn(n2.x, n2.y);
    __half2 h8p = __floats2half2_rn(n2.z, 0.0f);

    g_packed[f].a = make_uint4(*(unsigned*)&h01, *(unsigned*)&h23,
                               *(unsigned*)&h45, *(unsigned*)&h67);
    g_packed[f].b.x = *(unsigned*)&h8p;
}

// decode entry -> blended normal
__device__ __forceinline__ void blend_normal(uint4 A, unsigned B,
                                             float b0, float b1, float b2,
                                             float& nx, float& ny, float& nz)
{
    float2 p0 = __half22float2(*(__half2*)&A.x);  // n0x n0y
    float2 p1 = __half22float2(*(__half2*)&A.y);  // n0z n1x
    float2 p2 = __half22float2(*(__half2*)&A.z);  // n1y n1z
    float2 p3 = __half22float2(*(__half2*)&A.w);  // n2x n2y
    float2 p4 = __half22float2(*(__half2*)&B);    // n2z --
    nx = fmaf(b0, p0.x, fmaf(b1, p1.y, b2 * p3.x));
    ny = fmaf(b0, p0.y, fmaf(b1, p2.x, b2 * p3.y));
    nz = fmaf(b0, p1.x, fmaf(b1, p2.y, b2 * p4.x));
}

__global__ __launch_bounds__(BLK, 5)
void normal_shader_kernel(const int*   __restrict__ p2f,
                          const float* __restrict__ bary,
                          const float* __restrict__ zbuf,
                          const float* __restrict__ dists,
                          float*       __restrict__ out,
                          int npix)
{
    __shared__ float s[BLK * PPT * 3];

    const float ZFAR = 100.0f;
    const float INV_ZRANGE = 1.0f / 99.0f;
    const float INV_SIGMA = 1.0e4f;
    const float INV_GAMMA = 1.0e4f;
    const float EPS = 1.0e-10f;
    const float BGDIR = 0.577350269f;

    int tid  = threadIdx.x;
    int base = blockIdx.x * (BLK * PPT);

    #pragma unroll
    for (int p = 0; p < PPT; p++) {
        int pix  = base + p * BLK + tid;
        int pixc = (pix < npix) ? pix : 0;

        int4   f0 = reinterpret_cast<const int4*  >(p2f )[pixc * 2 + 0];
        int4   f1 = reinterpret_cast<const int4*  >(p2f )[pixc * 2 + 1];
        float4 z0 = reinterpret_cast<const float4*>(zbuf)[pixc * 2 + 0];
        float4 z1 = reinterpret_cast<const float4*>(zbuf)[pixc * 2 + 1];

        int   pf[K_SAMP] = {f0.x, f0.y, f0.z, f0.w, f1.x, f1.y, f1.z, f1.w};
        float zv[K_SAMP] = {z0.x, z0.y, z0.z, z0.w, z1.x, z1.y, z1.z, z1.w};

        float zinv[K_SAMP];
        float zmax = 0.0f;
        int   ksel = -1;
        int   fsel = 0;
        #pragma unroll
        for (int k = 0; k < K_SAMP; k++) {
            float zi = (pf[k] >= 0) ? (ZFAR - zv[k]) * INV_ZRANGE : 0.0f;
            zinv[k] = zi;
            if (zi > zmax) { zmax = zi; ksel = k; fsel = pf[k]; }
        }
        bool valid = (ksel >= 0);

        // ---- unconditional gather: one 32B entry (single cache line) ----
        int f = valid ? fsel : 0;
        uint4    A = g_packed[f].a;
        unsigned B = g_packed[f].b.x;

        int bb = (pixc * K_SAMP + (valid ? ksel : 0)) * 3;
        float b0 = bary[bb + 0];
        float b1 = bary[bb + 1];
        float b2 = bary[bb + 2];

        float nx, ny, nz;
        blend_normal(A, B, b0, b1, b2, nx, ny, nz);

        // ---- near-tie detection (e^-10 ~ 4.5e-5 << tol) ----
        float thresh = zmax - 1.0e-3f;
        bool ties = false;
        #pragma unroll
        for (int k = 0; k < K_SAMP; k++)
            ties |= (k != ksel && pf[k] >= 0 && zinv[k] > thresh);

        float vx, vy, vz;
        if (!valid) {
            vx = BGDIR; vy = BGDIR; vz = BGDIR;
        } else if (!ties && zmax >= 2.4e-3f) {
            vx = nx; vy = ny; vz = nz;
        } else {
            // SLOW (rare): full softmax blend
            float zm = fmaxf(zmax, EPS);
            float delta = EPS;
            if (zmax < 2.4e-3f)
                delta = fmaxf(__expf((EPS - zm) * INV_GAMMA), EPS);

            float4 d0 = reinterpret_cast<const float4*>(dists)[pixc * 2 + 0];
            float4 d1 = reinterpret_cast<const float4*>(dists)[pixc * 2 + 1];
            float dv[K_SAMP] = {d0.x, d0.y, d0.z, d0.w, d1.x, d1.y, d1.z, d1.w};

            float ax = 0.0f, ay = 0.0f, az = 0.0f;
            float lim = zm - 3.0e-3f;
            #pragma unroll
            for (int k = 0; k < K_SAMP; k++) {
                if (pf[k] < 0 || zinv[k] <= lim) continue;
                float ew = __expf((zinv[k] - zm) * INV_GAMMA);
                float prob = 1.0f / (1.0f + __expf(dv[k] * INV_SIGMA));
                float w = prob * ew;

                int ff = pf[k];
                uint4    MA = g_packed[ff].a;
                unsigned MB = g_packed[ff].b.x;

                int bk = (pixc * K_SAMP + k) * 3;
                float c0 = bary[bk + 0];
                float c1 = bary[bk + 1];
                float c2 = bary[bk + 2];

                float gx, gy, gz;
                blend_normal(MA, MB, c0, c1, c2, gx, gy, gz);

                ax = fmaf(w, gx, ax);
                ay = fmaf(w, gy, ay);
                az = fmaf(w, gz, az);
            }
            vx = ax + delta;
            vy = ay + delta;
            vz = az + delta;
        }

        float nn  = fmaf(vx, vx, fmaf(vy, vy, vz * vz));
        float inv = rsqrtf(fmaxf(nn, 1e-24f));
        int si = (p * BLK + tid) * 3;
        s[si + 0] = fmaf(vx * inv, 0.5f, 0.5f);
        s[si + 1] = fmaf(vy * inv, 0.5f, 0.5f);
        s[si + 2] = fmaf(vz * inv, 0.5f, 0.5f);
    }

    __syncthreads();

    // ---- coalesced float4 stores ----
    const int NF  = BLK * PPT * 3;       // 1536 floats
    const int NV4 = NF / 4;              // 384
    long fbase  = (long)blockIdx.x * NF;
    long ftotal = (long)npix * 3;
    if (fbase + NF <= ftotal) {
        #pragma unroll
        for (int i = tid; i < NV4; i += BLK) {
            reinterpret_cast<float4*>(out)[fbase / 4 + i] =
                reinterpret_cast<const float4*>(s)[i];
        }
    } else {
        for (int i = tid; i < NF; i += BLK) {
            long fi = fbase + i;
            if (fi < ftotal) out[fi] = s[i];
        }
    }
}

extern "C" void kernel_launch(void* const* d_in, const int* in_sizes, int n_in,
                              void* d_out, int out_size)
{
    const int*   p2f   = (const int*  )d_in[0];
    const float* bary  = (const float*)d_in[1];
    const float* zbuf  = (const float*)d_in[2];
    const float* dists = (const float*)d_in[3];
    const float* vnorm = (const float*)d_in[4];
    const int*   faces = (const int*  )d_in[5];
    float* out = (float*)d_out;

    int V = in_sizes[4] / 3;
    if (V > V_MAX) V = V_MAX;
    int F = in_sizes[5] / 3;
    if (F > F_MAX) F = F_MAX;
    int npix = in_sizes[0] / K_SAMP;

    expand_vnorm_kernel<<<(V + 255) / 256, 256>>>(vnorm, V);
    pack_faces_kernel<<<(F + 255) / 256, 256>>>(faces, F);

    int blocks = (npix + BLK * PPT - 1) / (BLK * PPT);
    normal_shader_kernel<<<blocks, BLK>>>(p2f, bary, zbuf, dists, out, npix);
}

// round 15
// speedup vs baseline: 1.0338x; 1.0338x over previous
#include <cuda_runtime.h>
#include <cuda_fp16.h>

// NormalShader fused, R15: main kernel identical to R10/R13 (33.3us).
// Pack kernel reads each 12B vnorm row through a uint4 window:
// 1 unconditional + 1 predicated LDG.128 (~1.5 wavefronts/vertex vs 3
// scalar) -> pack wavefront count nearly halved. No extra kernel nodes.

#define K_SAMP 8
#define BLK 256
#define PPT 2
#define F_MAX 200000

struct __align__(32) PackedFace {
    uint4 a;   // h0..h7 = n0x n0y n0z n1x n1y n1z n2x n2y
    uint4 b;   // b.x low half = n2z; rest pad (never read)
};

__device__ PackedFace g_packed[F_MAX];   // 6.4 MB, L2-resident

// Load vnorm row v (12B @ 4B alignment) via 16B-window loads.
__device__ __forceinline__ void load_vrow(const uint4* __restrict__ vn,
                                          int v, int nwords,
                                          float& x, float& y, float& z)
{
    int byte = v * 12;
    int w0   = byte >> 4;
    int o    = byte & 12;              // 0,4,8,12
    uint4 A  = vn[w0];
    uint4 Bv = make_uint4(0u, 0u, 0u, 0u);
    if (o >= 8) {                      // row spills into next word
        int w1 = w0 + 1;
        if (w1 < nwords) Bv = vn[w1];
    }
    float e0 = __uint_as_float(A.x);
    float e1 = __uint_as_float(A.y);
    float e2 = __uint_as_float(A.z);
    float e3 = __uint_as_float(A.w);
    float e4 = __uint_as_float(Bv.x);
    float e5 = __uint_as_float(Bv.y);
    x = (o == 0) ? e0 : (o == 4) ? e1 : (o == 8) ? e2 : e3;
    y = (o == 0) ? e1 : (o == 4) ? e2 : (o == 8) ? e3 : e4;
    z = (o == 0) ? e2 : (o == 4) ? e3 : (o == 8) ? e4 : e5;
}

__global__ __launch_bounds__(256)
void pack_faces_kernel(const int*   __restrict__ faces,
                       const float* __restrict__ vnorm,
                       int F, int nwords)
{
    const uint4* vn = reinterpret_cast<const uint4*>(vnorm);
    int f = blockIdx.x * blockDim.x + threadIdx.x;
    if (f >= F) return;
    int v0 = faces[f * 3 + 0];
    int v1 = faces[f * 3 + 1];
    int v2 = faces[f * 3 + 2];

    float a0, a1, a2, b0, b1, b2, c0, c1, c2;
    load_vrow(vn, v0, nwords, a0, a1, a2);
    load_vrow(vn, v1, nwords, b0, b1, b2);
    load_vrow(vn, v2, nwords, c0, c1, c2);

    __half2 h01 = __floats2half2_rn(a0, a1);
    __half2 h23 = __floats2half2_rn(a2, b0);
    __half2 h45 = __floats2half2_rn(b1, b2);
    __half2 h67 = __floats2half2_rn(c0, c1);
    __half2 h8p = __floats2half2_rn(c2, 0.0f);

    g_packed[f].a = make_uint4(*(unsigned*)&h01, *(unsigned*)&h23,
                               *(unsigned*)&h45, *(unsigned*)&h67);
    g_packed[f].b.x = *(unsigned*)&h8p;
}

// decode entry -> blended normal
__device__ __forceinline__ void blend_normal(uint4 A, unsigned B,
                                             float b0, float b1, float b2,
                                             float& nx, float& ny, float& nz)
{
    float2 p0 = __half22float2(*(__half2*)&A.x);  // n0x n0y
    float2 p1 = __half22float2(*(__half2*)&A.y);  // n0z n1x
    float2 p2 = __half22float2(*(__half2*)&A.z);  // n1y n1z
    float2 p3 = __half22float2(*(__half2*)&A.w);  // n2x n2y
    float2 p4 = __half22float2(*(__half2*)&B);    // n2z --
    nx = fmaf(b0, p0.x, fmaf(b1, p1.y, b2 * p3.x));
    ny = fmaf(b0, p0.y, fmaf(b1, p2.x, b2 * p3.y));
    nz = fmaf(b0, p1.x, fmaf(b1, p2.y, b2 * p4.x));
}

__global__ __launch_bounds__(BLK, 5)
void normal_shader_kernel(const int*   __restrict__ p2f,
                          const float* __restrict__ bary,
                          const float* __restrict__ zbuf,
                          const float* __restrict__ dists,
                          float*       __restrict__ out,
                          int npix)
{
    __shared__ float s[BLK * PPT * 3];

    const float ZFAR = 100.0f;
    const float INV_ZRANGE = 1.0f / 99.0f;
    const float INV_SIGMA = 1.0e4f;
    const float INV_GAMMA = 1.0e4f;
    const float EPS = 1.0e-10f;
    const float BGDIR = 0.577350269f;

    int tid  = threadIdx.x;
    int base = blockIdx.x * (BLK * PPT);

    #pragma unroll
    for (int p = 0; p < PPT; p++) {
        int pix  = base + p * BLK + tid;
        int pixc = (pix < npix) ? pix : 0;

        int4   f0 = reinterpret_cast<const int4*  >(p2f )[pixc * 2 + 0];
        int4   f1 = reinterpret_cast<const int4*  >(p2f )[pixc * 2 + 1];
        float4 z0 = reinterpret_cast<const float4*>(zbuf)[pixc * 2 + 0];
        float4 z1 = reinterpret_cast<const float4*>(zbuf)[pixc * 2 + 1];

        int   pf[K_SAMP] = {f0.x, f0.y, f0.z, f0.w, f1.x, f1.y, f1.z, f1.w};
        float zv[K_SAMP] = {z0.x, z0.y, z0.z, z0.w, z1.x, z1.y, z1.z, z1.w};

        float zinv[K_SAMP];
        float zmax = 0.0f;
        int   ksel = -1;
        int   fsel = 0;
        #pragma unroll
        for (int k = 0; k < K_SAMP; k++) {
            float zi = (pf[k] >= 0) ? (ZFAR - zv[k]) * INV_ZRANGE : 0.0f;
            zinv[k] = zi;
            if (zi > zmax) { zmax = zi; ksel = k; fsel = pf[k]; }
        }
        bool valid = (ksel >= 0);

        // ---- unconditional gather: one 32B entry (single cache line) ----
        int f = valid ? fsel : 0;
        uint4    A = g_packed[f].a;
        unsigned B = g_packed[f].b.x;

        int bb = (pixc * K_SAMP + (valid ? ksel : 0)) * 3;
        float b0 = bary[bb + 0];
        float b1 = bary[bb + 1];
        float b2 = bary[bb + 2];

        float nx, ny, nz;
        blend_normal(A, B, b0, b1, b2, nx, ny, nz);

        // ---- near-tie detection (e^-10 ~ 4.5e-5 << tol) ----
        float thresh = zmax - 1.0e-3f;
        bool ties = false;
        #pragma unroll
        for (int k = 0; k < K_SAMP; k++)
            ties |= (k != ksel && pf[k] >= 0 && zinv[k] > thresh);

        float vx, vy, vz;
        if (!valid) {
            vx = BGDIR; vy = BGDIR; vz = BGDIR;
        } else if (!ties && zmax >= 2.4e-3f) {
            vx = nx; vy = ny; vz = nz;
        } else {
            // SLOW (rare): full softmax blend
            float zm = fmaxf(zmax, EPS);
            float delta = EPS;
            if (zmax < 2.4e-3f)
                delta = fmaxf(__expf((EPS - zm) * INV_GAMMA), EPS);

            float4 d0 = reinterpret_cast<const float4*>(dists)[pixc * 2 + 0];
            float4 d1 = reinterpret_cast<const float4*>(dists)[pixc * 2 + 1];
            float dv[K_SAMP] = {d0.x, d0.y, d0.z, d0.w, d1.x, d1.y, d1.z, d1.w};

            float ax = 0.0f, ay = 0.0f, az = 0.0f;
            float lim = zm - 3.0e-3f;
            #pragma unroll
            for (int k = 0; k < K_SAMP; k++) {
                if (pf[k] < 0 || zinv[k] <= lim) continue;
                float ew = __expf((zinv[k] - zm) * INV_GAMMA);
                float prob = 1.0f / (1.0f + __expf(dv[k] * INV_SIGMA));
                float w = prob * ew;

                int ff = pf[k];
                uint4    MA = g_packed[ff].a;
                unsigned MB = g_packed[ff].b.x;

                int bk = (pixc * K_SAMP + k) * 3;
                float c0 = bary[bk + 0];
                float c1 = bary[bk + 1];
                float c2 = bary[bk + 2];

                float gx, gy, gz;
                blend_normal(MA, MB, c0, c1, c2, gx, gy, gz);

                ax = fmaf(w, gx, ax);
                ay = fmaf(w, gy, ay);
                az = fmaf(w, gz, az);
            }
            vx = ax + delta;
            vy = ay + delta;
            vz = az + delta;
        }

        float nn  = fmaf(vx, vx, fmaf(vy, vy, vz * vz));
        float inv = rsqrtf(fmaxf(nn, 1e-24f));
        int si = (p * BLK + tid) * 3;
        s[si + 0] = fmaf(vx * inv, 0.5f, 0.5f);
        s[si + 1] = fmaf(vy * inv, 0.5f, 0.5f);
        s[si + 2] = fmaf(vz * inv, 0.5f, 0.5f);
    }

    __syncthreads();

    // ---- coalesced float4 stores ----
    const int NF  = BLK * PPT * 3;       // 1536 floats
    const int NV4 = NF / 4;              // 384
    long fbase  = (long)blockIdx.x * NF;
    long ftotal = (long)npix * 3;
    if (fbase + NF <= ftotal) {
        #pragma unroll
        for (int i = tid; i < NV4; i += BLK) {
            reinterpret_cast<float4*>(out)[fbase / 4 + i] =
                reinterpret_cast<const float4*>(s)[i];
        }
    } else {
        for (int i = tid; i < NF; i += BLK) {
            long fi = fbase + i;
            if (fi < ftotal) out[fi] = s[i];
        }
    }
}

extern "C" void kernel_launch(void* const* d_in, const int* in_sizes, int n_in,
                              void* d_out, int out_size)
{
    const int*   p2f   = (const int*  )d_in[0];
    const float* bary  = (const float*)d_in[1];
    const float* zbuf  = (const float*)d_in[2];
    const float* dists = (const float*)d_in[3];
    const float* vnorm = (const float*)d_in[4];
    const int*   faces = (const int*  )d_in[5];
    float* out = (float*)d_out;

    int F = in_sizes[5] / 3;
    if (F > F_MAX) F = F_MAX;
    int nwords = in_sizes[4] / 4;            // full 16B words in vnorm
    int npix = in_sizes[0] / K_SAMP;

    pack_faces_kernel<<<(F + 255) / 256, 256>>>(faces, vnorm, F, nwords);

    int blocks = (npix + BLK * PPT - 1) / (BLK * PPT);
    normal_shader_kernel<<<blocks, BLK>>>(p2f, bary, zbuf, dists, out, npix);
}

// round 16
// speedup vs baseline: 1.0499x; 1.0156x over previous
#include <cuda_runtime.h>
#include <cuda_fp16.h>

// NormalShader fused, R16: R10/R13 main kernel with ONE change — streaming
// cache hints (__ldcs) on the read-once row streams and (__stcs) on the
// output, so L2 retains the randomly-gathered g_packed table instead of
// being flushed by 128MB of stream data. Pack kernel = R15.

#define K_SAMP 8
#define BLK 256
#define PPT 2
#define F_MAX 200000

struct __align__(32) PackedFace {
    uint4 a;   // h0..h7 = n0x n0y n0z n1x n1y n1z n2x n2y
    uint4 b;   // b.x low half = n2z; rest pad (never read)
};

__device__ PackedFace g_packed[F_MAX];   // 6.4 MB, L2-resident

// Load vnorm row v (12B @ 4B alignment) via 16B-window loads.
__device__ __forceinline__ void load_vrow(const uint4* __restrict__ vn,
                                          int v, int nwords,
                                          float& x, float& y, float& z)
{
    int byte = v * 12;
    int w0   = byte >> 4;
    int o    = byte & 12;              // 0,4,8,12
    uint4 A  = vn[w0];
    uint4 Bv = make_uint4(0u, 0u, 0u, 0u);
    if (o >= 8) {                      // row spills into next word
        int w1 = w0 + 1;
        if (w1 < nwords) Bv = vn[w1];
    }
    float e0 = __uint_as_float(A.x);
    float e1 = __uint_as_float(A.y);
    float e2 = __uint_as_float(A.z);
    float e3 = __uint_as_float(A.w);
    float e4 = __uint_as_float(Bv.x);
    float e5 = __uint_as_float(Bv.y);
    x = (o == 0) ? e0 : (o == 4) ? e1 : (o == 8) ? e2 : e3;
    y = (o == 0) ? e1 : (o == 4) ? e2 : (o == 8) ? e3 : e4;
    z = (o == 0) ? e2 : (o == 4) ? e3 : (o == 8) ? e4 : e5;
}

__global__ __launch_bounds__(256)
void pack_faces_kernel(const int*   __restrict__ faces,
                       const float* __restrict__ vnorm,
                       int F, int nwords)
{
    const uint4* vn = reinterpret_cast<const uint4*>(vnorm);
    int f = blockIdx.x * blockDim.x + threadIdx.x;
    if (f >= F) return;
    int v0 = faces[f * 3 + 0];
    int v1 = faces[f * 3 + 1];
    int v2 = faces[f * 3 + 2];

    float a0, a1, a2, b0, b1, b2, c0, c1, c2;
    load_vrow(vn, v0, nwords, a0, a1, a2);
    load_vrow(vn, v1, nwords, b0, b1, b2);
    load_vrow(vn, v2, nwords, c0, c1, c2);

    __half2 h01 = __floats2half2_rn(a0, a1);
    __half2 h23 = __floats2half2_rn(a2, b0);
    __half2 h45 = __floats2half2_rn(b1, b2);
    __half2 h67 = __floats2half2_rn(c0, c1);
    __half2 h8p = __floats2half2_rn(c2, 0.0f);

    g_packed[f].a = make_uint4(*(unsigned*)&h01, *(unsigned*)&h23,
                               *(unsigned*)&h45, *(unsigned*)&h67);
    g_packed[f].b.x = *(unsigned*)&h8p;
}

// decode entry -> blended normal
__device__ __forceinline__ void blend_normal(uint4 A, unsigned B,
                                             float b0, float b1, float b2,
                                             float& nx, float& ny, float& nz)
{
    float2 p0 = __half22float2(*(__half2*)&A.x);  // n0x n0y
    float2 p1 = __half22float2(*(__half2*)&A.y);  // n0z n1x
    float2 p2 = __half22float2(*(__half2*)&A.z);  // n1y n1z
    float2 p3 = __half22float2(*(__half2*)&A.w);  // n2x n2y
    float2 p4 = __half22float2(*(__half2*)&B);    // n2z --
    nx = fmaf(b0, p0.x, fmaf(b1, p1.y, b2 * p3.x));
    ny = fmaf(b0, p0.y, fmaf(b1, p2.x, b2 * p3.y));
    nz = fmaf(b0, p1.x, fmaf(b1, p2.y, b2 * p4.x));
}

__global__ __launch_bounds__(BLK, 5)
void normal_shader_kernel(const int*   __restrict__ p2f,
                          const float* __restrict__ bary,
                          const float* __restrict__ zbuf,
                          const float* __restrict__ dists,
                          float*       __restrict__ out,
                          int npix)
{
    __shared__ float s[BLK * PPT * 3];

    const float ZFAR = 100.0f;
    const float INV_ZRANGE = 1.0f / 99.0f;
    const float INV_SIGMA = 1.0e4f;
    const float INV_GAMMA = 1.0e4f;
    const float EPS = 1.0e-10f;
    const float BGDIR = 0.577350269f;

    int tid  = threadIdx.x;
    int base = blockIdx.x * (BLK * PPT);

    #pragma unroll
    for (int p = 0; p < PPT; p++) {
        int pix  = base + p * BLK + tid;
        int pixc = (pix < npix) ? pix : 0;

        // read-once streams: evict-first so L2 keeps the face table
        int4   f0 = __ldcs(reinterpret_cast<const int4*  >(p2f ) + pixc * 2 + 0);
        int4   f1 = __ldcs(reinterpret_cast<const int4*  >(p2f ) + pixc * 2 + 1);
        float4 z0 = __ldcs(reinterpret_cast<const float4*>(zbuf) + pixc * 2 + 0);
        float4 z1 = __ldcs(reinterpret_cast<const float4*>(zbuf) + pixc * 2 + 1);

        int   pf[K_SAMP] = {f0.x, f0.y, f0.z, f0.w, f1.x, f1.y, f1.z, f1.w};
        float zv[K_SAMP] = {z0.x, z0.y, z0.z, z0.w, z1.x, z1.y, z1.z, z1.w};

        float zinv[K_SAMP];
        float zmax = 0.0f;
        int   ksel = -1;
        int   fsel = 0;
        #pragma unroll
        for (int k = 0; k < K_SAMP; k++) {
            float zi = (pf[k] >= 0) ? (ZFAR - zv[k]) * INV_ZRANGE : 0.0f;
            zinv[k] = zi;
            if (zi > zmax) { zmax = zi; ksel = k; fsel = pf[k]; }
        }
        bool valid = (ksel >= 0);

        // ---- unconditional gather: one 32B entry (single cache line) ----
        int f = valid ? fsel : 0;
        uint4    A = g_packed[f].a;
        unsigned B = g_packed[f].b.x;

        int bb = (pixc * K_SAMP + (valid ? ksel : 0)) * 3;
        float b0 = bary[bb + 0];
        float b1 = bary[bb + 1];
        float b2 = bary[bb + 2];

        float nx, ny, nz;
        blend_normal(A, B, b0, b1, b2, nx, ny, nz);

        // ---- near-tie detection (e^-10 ~ 4.5e-5 << tol) ----
        float thresh = zmax - 1.0e-3f;
        bool ties = false;
        #pragma unroll
        for (int k = 0; k < K_SAMP; k++)
            ties |= (k != ksel && pf[k] >= 0 && zinv[k] > thresh);

        float vx, vy, vz;
        if (!valid) {
            vx = BGDIR; vy = BGDIR; vz = BGDIR;
        } else if (!ties && zmax >= 2.4e-3f) {
            vx = nx; vy = ny; vz = nz;
        } else {
            // SLOW (rare): full softmax blend
            float zm = fmaxf(zmax, EPS);
            float delta = EPS;
            if (zmax < 2.4e-3f)
                delta = fmaxf(__expf((EPS - zm) * INV_GAMMA), EPS);

            float4 d0 = __ldcs(reinterpret_cast<const float4*>(dists) + pixc * 2 + 0);
            float4 d1 = __ldcs(reinterpret_cast<const float4*>(dists) + pixc * 2 + 1);
            float dv[K_SAMP] = {d0.x, d0.y, d0.z, d0.w, d1.x, d1.y, d1.z, d1.w};

            float ax = 0.0f, ay = 0.0f, az = 0.0f;
            float lim = zm - 3.0e-3f;
            #pragma unroll
            for (int k = 0; k < K_SAMP; k++) {
                if (pf[k] < 0 || zinv[k] <= lim) continue;
                float ew = __expf((zinv[k] - zm) * INV_GAMMA);
                float prob = 1.0f / (1.0f + __expf(dv[k] * INV_SIGMA));
                float w = prob * ew;

                int ff = pf[k];
                uint4    MA = g_packed[ff].a;
                unsigned MB = g_packed[ff].b.x;

                int bk = (pixc * K_SAMP + k) * 3;
                float c0 = bary[bk + 0];
                float c1 = bary[bk + 1];
                float c2 = bary[bk + 2];

                float gx, gy, gz;
                blend_normal(MA, MB, c0, c1, c2, gx, gy, gz);

                ax = fmaf(w, gx, ax);
                ay = fmaf(w, gy, ay);
                az = fmaf(w, gz, az);
            }
            vx = ax + delta;
            vy = ay + delta;
            vz = az + delta;
        }

        float nn  = fmaf(vx, vx, fmaf(vy, vy, vz * vz));
        float inv = rsqrtf(fmaxf(nn, 1e-24f));
        int si = (p * BLK + tid) * 3;
        s[si + 0] = fmaf(vx * inv, 0.5f, 0.5f);
        s[si + 1] = fmaf(vy * inv, 0.5f, 0.5f);
        s[si + 2] = fmaf(vz * inv, 0.5f, 0.5f);
    }

    __syncthreads();

    // ---- coalesced float4 streaming stores ----
    const int NF  = BLK * PPT * 3;       // 1536 floats
    const int NV4 = NF / 4;              // 384
    long fbase  = (long)blockIdx.x * NF;
    long ftotal = (long)npix * 3;
    if (fbase + NF <= ftotal) {
        #pragma unroll
        for (int i = tid; i < NV4; i += BLK) {
            __stcs(reinterpret_cast<float4*>(out) + fbase / 4 + i,
                   reinterpret_cast<const float4*>(s)[i]);
        }
    } else {
        for (int i = tid; i < NF; i += BLK) {
            long fi = fbase + i;
            if (fi < ftotal) out[fi] = s[i];
        }
    }
}

extern "C" void kernel_launch(void* const* d_in, const int* in_sizes, int n_in,
                              void* d_out, int out_size)
{
    const int*   p2f   = (const int*  )d_in[0];
    const float* bary  = (const float*)d_in[1];
    const float* zbuf  = (const float*)d_in[2];
    const float* dists = (const float*)d_in[3];
    const float* vnorm = (const float*)d_in[4];
    const int*   faces = (const int*  )d_in[5];
    float* out = (float*)d_out;

    int F = in_sizes[5] / 3;
    if (F > F_MAX) F = F_MAX;
    int nwords = in_sizes[4] / 4;            // full 16B words in vnorm
    int npix = in_sizes[0] / K_SAMP;

    pack_faces_kernel<<<(F + 255) / 256, 256>>>(faces, vnorm, F, nwords);

    int blocks = (npix + BLK * PPT - 1) / (BLK * PPT);
    normal_shader_kernel<<<blocks, BLK>>>(p2f, bary, zbuf, dists, out, npix);
}